// round 2
// baseline (speedup 1.0000x reference)
#include <cuda_runtime.h>
#include <math_constants.h>
#include <cstdint>

#define D      768
#define BPREV  8192
#define BCUR   4096
#define KNB    5
#define CHUNKS 16
#define JT_PER_CHUNK 8   // 8 tiles * 64 cols = 512 cols per chunk; 16*512 = 8192
#define BM 128
#define BN 64
#define BK 16
#define NTHREADS 256

// ---------------- device scratch (no allocations allowed) ----------------
__device__ float g_hp[BPREV * D];                       // normalized previous
__device__ float g_hc[BCUR * D];                        // normalized current
__device__ float g_sq[BCUR];                            // sum(hc^2) per row
__device__ float g_cand_val[BCUR * CHUNKS * 2 * KNB];   // per (row, chunk, half) top-5
__device__ int   g_cand_idx[BCUR * CHUNKS * 2 * KNB];
__device__ int   g_nbr[BCUR * KNB];                     // final 5 neighbors per row

// ---------------- helpers ----------------
__device__ __forceinline__ bool better(float v1, int j1, float v2, int j2) {
    // JAX top_k order: larger value wins; tie -> smaller index
    return (v1 > v2) || (v1 == v2 && j1 < j2);
}

__device__ __forceinline__ void insert5(float v, int j, float* tv, int* tj) {
    if (!better(v, j, tv[KNB - 1], tj[KNB - 1])) return;
    tv[KNB - 1] = v; tj[KNB - 1] = j;
#pragma unroll
    for (int k = KNB - 1; k > 0; --k) {
        if (better(tv[k], tj[k], tv[k - 1], tj[k - 1])) {
            float fv = tv[k]; tv[k] = tv[k - 1]; tv[k - 1] = fv;
            int   ij = tj[k]; tj[k] = tj[k - 1]; tj[k - 1] = ij;
        }
    }
}

// ---------------- kernels ----------------
__global__ void zero_out(float* out) { out[0] = 0.0f; }

// One block per row: y = x / max(||x||, eps); optionally sq_out[r] = sum(y^2)
__global__ void normalize_rows(const float* __restrict__ src,
                               float* __restrict__ dst,
                               float* __restrict__ sq_out) {
    int r = blockIdx.x;
    const float* x = src + (size_t)r * D;
    float* y = dst + (size_t)r * D;
    __shared__ float red[256];
    float s = 0.f;
    for (int k = threadIdx.x; k < D; k += 256) { float v = x[k]; s += v * v; }
    red[threadIdx.x] = s;
    __syncthreads();
    for (int off = 128; off > 0; off >>= 1) {
        if (threadIdx.x < off) red[threadIdx.x] += red[threadIdx.x + off];
        __syncthreads();
    }
    float denom = fmaxf(sqrtf(red[0]), 1e-12f);
    float s2 = 0.f;
    for (int k = threadIdx.x; k < D; k += 256) {
        float v = x[k] / denom;
        y[k] = v;
        s2 += v * v;
    }
    if (sq_out != nullptr) {
        __syncthreads();
        red[threadIdx.x] = s2;
        __syncthreads();
        for (int off = 128; off > 0; off >>= 1) {
            if (threadIdx.x < off) red[threadIdx.x] += red[threadIdx.x + off];
            __syncthreads();
        }
        if (threadIdx.x == 0) sq_out[r] = red[0];
    }
}

// kNN GEMM + streaming top-5.
// grid = (BCUR/BM, CHUNKS). Each block: 128 i-rows x 512 j-cols (8 tiles of 64).
__global__ void __launch_bounds__(NTHREADS) knn_kernel() {
    __shared__ float As[BK][BM + 4];   // transposed: As[kk][row]
    __shared__ float Bs[BK][BN + 4];
    __shared__ float Sim[BM][BN + 4];

    const int tid   = threadIdx.x;
    const int i0    = blockIdx.x * BM;
    const int chunk = blockIdx.y;
    const int jbase = chunk * (JT_PER_CHUNK * BN);
    const int ty = tid >> 4;          // 0..15 -> rows ty*8..ty*8+7
    const int tx = tid & 15;          // 0..15 -> cols tx*4..tx*4+3

    // per-thread top-5 state (2 threads per row: halves of the 64-col tile)
    const int row  = tid >> 1;        // 0..127
    const int half = tid & 1;         // scans cols [half*32, half*32+32)
    const int ig   = i0 + row;        // global i of my row

    float tv[KNB]; int tj[KNB];
#pragma unroll
    for (int k = 0; k < KNB; k++) { tv[k] = -CUDART_INF_F; tj[k] = 0x7fffffff; }

    for (int t = 0; t < JT_PER_CHUNK; t++) {
        const int j0 = jbase + t * BN;
        float acc[8][4];
#pragma unroll
        for (int r = 0; r < 8; r++)
#pragma unroll
            for (int c = 0; c < 4; c++) acc[r][c] = 0.f;

        for (int k0 = 0; k0 < D; k0 += BK) {
            // load A tile: 128 rows x 16 k -> 512 float4, 2 per thread, transposed
#pragma unroll
            for (int q = 0; q < 2; q++) {
                int idx = tid + q * 256;
                int r = idx >> 2, k4 = idx & 3;
                float4 v = *(const float4*)&g_hp[(size_t)(i0 + r) * D + k0 + k4 * 4];
                As[k4 * 4 + 0][r] = v.x; As[k4 * 4 + 1][r] = v.y;
                As[k4 * 4 + 2][r] = v.z; As[k4 * 4 + 3][r] = v.w;
            }
            // load B tile: 64 rows x 16 k -> 256 float4, 1 per thread, transposed
            {
                int r = tid >> 2, k4 = tid & 3;
                float4 v = *(const float4*)&g_hp[(size_t)(j0 + r) * D + k0 + k4 * 4];
                Bs[k4 * 4 + 0][r] = v.x; Bs[k4 * 4 + 1][r] = v.y;
                Bs[k4 * 4 + 2][r] = v.z; Bs[k4 * 4 + 3][r] = v.w;
            }
            __syncthreads();
#pragma unroll
            for (int kk = 0; kk < BK; kk++) {
                float4 a0 = *(const float4*)&As[kk][ty * 8];
                float4 a1 = *(const float4*)&As[kk][ty * 8 + 4];
                float4 b0 = *(const float4*)&Bs[kk][tx * 4];
                float a[8] = {a0.x, a0.y, a0.z, a0.w, a1.x, a1.y, a1.z, a1.w};
                float b[4] = {b0.x, b0.y, b0.z, b0.w};
#pragma unroll
                for (int r = 0; r < 8; r++)
#pragma unroll
                    for (int c = 0; c < 4; c++)
                        acc[r][c] = fmaf(a[r], b[c], acc[r][c]);
            }
            __syncthreads();
        }

        // stage sims to smem
#pragma unroll
        for (int r = 0; r < 8; r++) {
            *(float4*)&Sim[ty * 8 + r][tx * 4] =
                make_float4(acc[r][0], acc[r][1], acc[r][2], acc[r][3]);
        }
        __syncthreads();

        // scan my half-row, maintain top-5 (exclude self)
#pragma unroll 8
        for (int c0 = 0; c0 < 32; c0++) {
            int c = half * 32 + c0;
            float v = Sim[row][c];
            int jg = j0 + c;
            if (jg != ig) insert5(v, jg, tv, tj);
        }
        __syncthreads();
    }

    // write candidate list
    size_t base = ((size_t)ig * (CHUNKS * 2) + (size_t)chunk * 2 + half) * KNB;
#pragma unroll
    for (int k = 0; k < KNB; k++) {
        g_cand_val[base + k] = tv[k];
        g_cand_idx[base + k] = tj[k];
    }
}

// merge CHUNKS*2 candidate lists per row -> final top-5
__global__ void merge_kernel() {
    int i = blockIdx.x * blockDim.x + threadIdx.x;
    if (i >= BCUR) return;
    float tv[KNB]; int tj[KNB];
#pragma unroll
    for (int k = 0; k < KNB; k++) { tv[k] = -CUDART_INF_F; tj[k] = 0x7fffffff; }
    size_t base = (size_t)i * (CHUNKS * 2 * KNB);
    for (int c = 0; c < CHUNKS * 2 * KNB; c++) {
        insert5(g_cand_val[base + c], g_cand_idx[base + c], tv, tj);
    }
#pragma unroll
    for (int k = 0; k < KNB; k++) g_nbr[i * KNB + k] = tj[k];
}

// one block per row i; warp w handles neighbor w
// NOTE: labels are int32 on-device (jax x64 disabled downgrades jnp.int64).
__global__ void contrib_kernel(const int* __restrict__ lprev,
                               float* __restrict__ out) {
    int i = blockIdx.x;
    int w = threadIdx.x >> 5;
    int lane = threadIdx.x & 31;
    if (w >= KNB) return;
    int j = g_nbr[i * KNB + w];
    if (j >= BCUR) return;   // only affinity[:4096,:4096] contributes
    const float* xi = g_hc + (size_t)i * D;
    const float* xj = g_hc + (size_t)j * D;
    float s = 0.f;
#pragma unroll 4
    for (int k = lane; k < D; k += 32) s = fmaf(xi[k], xj[k], s);
#pragma unroll
    for (int off = 16; off; off >>= 1) s += __shfl_down_sync(0xffffffffu, s, off);
    if (lane == 0) {
        float d2 = g_sq[i] + g_sq[j] - 2.f * s;
        d2 = fmaxf(d2, 0.f);
        float e = (lprev[i] == lprev[j]) ? 1.f : -1.f;
        const float scale = 0.5f / ((float)BCUR * (float)BCUR);  // WEIGHT / B^2
        atomicAdd(out, e * d2 * scale);
    }
}

// ---------------- launcher ----------------
extern "C" void kernel_launch(void* const* d_in, const int* in_sizes, int n_in,
                              void* d_out, int out_size) {
    const float* hidden_current  = (const float*)d_in[0];       // 4096*768
    const float* hidden_previous = (const float*)d_in[1];       // 8192*768
    // d_in[2] = labels_current (unused by the reference loss)
    const int* labels_previous   = (const int*)d_in[3];         // int32 (jax x64 off)
    float* out = (float*)d_out;

    float* hp = nullptr; float* hc = nullptr; float* sq = nullptr;
    cudaGetSymbolAddress((void**)&hp, g_hp);
    cudaGetSymbolAddress((void**)&hc, g_hc);
    cudaGetSymbolAddress((void**)&sq, g_sq);

    zero_out<<<1, 1>>>(out);
    normalize_rows<<<BPREV, 256>>>(hidden_previous, hp, nullptr);
    normalize_rows<<<BCUR, 256>>>(hidden_current, hc, sq);
    knn_kernel<<<dim3(BCUR / BM, CHUNKS), NTHREADS>>>();
    merge_kernel<<<(BCUR + 255) / 256, 256>>>();
    contrib_kernel<<<BCUR, KNB * 32>>>(labels_previous, out);
}